// round 3
// baseline (speedup 1.0000x reference)
#include <cuda_runtime.h>
#include <cstdint>

// ---------------------------------------------------------------------------
// out = ((x @ (w1_q*s1)) @ (w2_q*s2)) per expert.  E=8, T=4096, H=2048.
// compute_103 PTX target => no tcgen05; legacy IMMA runs ~270 MAC/cyc/SM.
// Round-3 strategy: exact 16-bit activation split (hi,lo int8 planes).
//   hi-plane GEMM  -> tensor pipe (mma.sync m16n8k32 s8)
//   lo-plane GEMM  -> DP4A on the idle integer pipe, CONCURRENTLY
// out = (256*acc_hi + acc_lo) * s_row * wscale_col.
// ---------------------------------------------------------------------------

#define EE 8
#define TT 4096
#define HH 2048

#define BM 128
#define BN 128
#define BK 128
#define NKIT (HH / BK)          // 16
#define PLANE 16384             // one 128x128 s8 tile
#define STAGE (3 * PLANE)       // A_hi + A_lo + B
#define NSTAGE 3
#define DYNSMEM (NSTAGE * STAGE)  // 147456 B

// -------------------- scratch --------------------------------------------
__device__ int8_t g_w1t[(size_t)EE * HH * HH];   // w1^T int8 [E][n][k]
__device__ int8_t g_w2t[(size_t)EE * HH * HH];   // w2^T int8 [E][n][k]
__device__ int8_t g_ahi[(size_t)EE * TT * HH];   // activation hi bytes
__device__ int8_t g_alo[(size_t)EE * TT * HH];   // activation lo bytes
__device__ float  g_rs [(size_t)EE * TT];        // per-row dequant scale
__device__ float  g_h  [(size_t)EE * TT * HH];   // layer-1 output fp32

// -------------------- helpers --------------------------------------------
__device__ __forceinline__ uint32_t smem_u32(const void* p) {
    uint32_t a;
    asm("{ .reg .u64 t; cvta.to.shared.u64 t, %1; cvt.u32.u64 %0, t; }"
        : "=r"(a) : "l"(p));
    return a;
}

#define CP_ASYNC16(dst, src) \
    asm volatile("cp.async.cg.shared.global [%0], [%1], 16;" \
                 :: "r"(dst), "l"(src) : "memory")
#define CP_COMMIT() asm volatile("cp.async.commit_group;" ::: "memory")
#define CP_WAIT1()  asm volatile("cp.async.wait_group 1;" ::: "memory")
#define CP_WAIT0()  asm volatile("cp.async.wait_group 0;" ::: "memory")

__device__ __forceinline__ void imma(int* d, const uint32_t* a,
                                     const uint32_t* b) {
    asm volatile(
        "mma.sync.aligned.m16n8k32.row.col.s32.s8.s8.s32 "
        "{%0,%1,%2,%3},{%4,%5,%6,%7},{%8,%9},{%0,%1,%2,%3};"
        : "+r"(d[0]), "+r"(d[1]), "+r"(d[2]), "+r"(d[3])
        : "r"(a[0]), "r"(a[1]), "r"(a[2]), "r"(a[3]),
          "r"(b[0]), "r"(b[1]));
}

__device__ __forceinline__ int dp4a_(int a, int b, int c) {
    int d;
    asm("dp4a.s32.s32 %0, %1, %2, %3;" : "=r"(d) : "r"(a), "r"(b), "r"(c));
    return d;
}

// -------------------- weight convert + transpose --------------------------
// wq int32 [E][k][n] -> out int8 [E][n][k]
__global__ void convw_kernel(const int* __restrict__ W,
                             int8_t* __restrict__ O) {
    __shared__ int8_t tile[32][33];
    const int e  = blockIdx.z;
    const int n0 = blockIdx.x * 32;
    const int k0 = blockIdx.y * 32;
    const int tx = threadIdx.x, ty = threadIdx.y;

    const int* src = W + ((size_t)e * HH + k0) * HH + n0;
#pragma unroll
    for (int r = 0; r < 4; r++) {
        tile[ty + r * 8][tx] = (int8_t)src[(size_t)(ty + r * 8) * HH + tx];
    }
    __syncthreads();
    const int t  = ty * 32 + tx;        // 0..255
    const int nr = t >> 3;              // out row (n) 0..31
    const int c4 = (t & 7) * 4;         // k byte group
    uint32_t p = (uint32_t)(uint8_t)tile[c4 + 0][nr]
               | ((uint32_t)(uint8_t)tile[c4 + 1][nr] << 8)
               | ((uint32_t)(uint8_t)tile[c4 + 2][nr] << 16)
               | ((uint32_t)(uint8_t)tile[c4 + 3][nr] << 24);
    *(uint32_t*)(O + ((size_t)e * HH + n0 + nr) * HH + k0 + c4) = p;
}

// -------------------- activation quantize (16-bit split) -------------------
__global__ void quant_kernel(const float* __restrict__ X,
                             int8_t* __restrict__ Qh,
                             int8_t* __restrict__ Ql,
                             float* __restrict__ RS) {
    const int row = blockIdx.x;
    const float* x = X + (size_t)row * HH;
    const int tid = threadIdx.x;

    const float4 v0 = ((const float4*)x)[tid];
    const float4 v1 = ((const float4*)x)[tid + 256];

    float m = fabsf(v0.x);
    m = fmaxf(m, fabsf(v0.y)); m = fmaxf(m, fabsf(v0.z));
    m = fmaxf(m, fabsf(v0.w)); m = fmaxf(m, fabsf(v1.x));
    m = fmaxf(m, fabsf(v1.y)); m = fmaxf(m, fabsf(v1.z));
    m = fmaxf(m, fabsf(v1.w));
#pragma unroll
    for (int o = 16; o; o >>= 1)
        m = fmaxf(m, __shfl_xor_sync(0xFFFFFFFFu, m, o));
    __shared__ float wr[8];
    if ((tid & 31) == 0) wr[tid >> 5] = m;
    __syncthreads();
    float mx = wr[0];
#pragma unroll
    for (int j = 1; j < 8; j++) mx = fmaxf(mx, wr[j]);
    mx = fmaxf(mx, 1e-20f);
    const float inv = 32600.0f / mx;

    uint32_t* ph = (uint32_t*)(Qh + (size_t)row * HH);
    uint32_t* pl = (uint32_t*)(Ql + (size_t)row * HH);

    {
        const int q0 = __float2int_rn(v0.x * inv);
        const int q1 = __float2int_rn(v0.y * inv);
        const int q2 = __float2int_rn(v0.z * inv);
        const int q3 = __float2int_rn(v0.w * inv);
        const int h0 = (q0 + 128) >> 8, h1 = (q1 + 128) >> 8;
        const int h2 = (q2 + 128) >> 8, h3 = (q3 + 128) >> 8;
        const int l0 = q0 - (h0 << 8), l1 = q1 - (h1 << 8);
        const int l2 = q2 - (h2 << 8), l3 = q3 - (h3 << 8);
        ph[tid] = (h0 & 255) | ((h1 & 255) << 8) | ((h2 & 255) << 16)
                | ((uint32_t)(h3 & 255) << 24);
        pl[tid] = (l0 & 255) | ((l1 & 255) << 8) | ((l2 & 255) << 16)
                | ((uint32_t)(l3 & 255) << 24);
    }
    {
        const int q0 = __float2int_rn(v1.x * inv);
        const int q1 = __float2int_rn(v1.y * inv);
        const int q2 = __float2int_rn(v1.z * inv);
        const int q3 = __float2int_rn(v1.w * inv);
        const int h0 = (q0 + 128) >> 8, h1 = (q1 + 128) >> 8;
        const int h2 = (q2 + 128) >> 8, h3 = (q3 + 128) >> 8;
        const int l0 = q0 - (h0 << 8), l1 = q1 - (h1 << 8);
        const int l2 = q2 - (h2 << 8), l3 = q3 - (h3 << 8);
        ph[tid + 256] = (h0 & 255) | ((h1 & 255) << 8) | ((h2 & 255) << 16)
                      | ((uint32_t)(h3 & 255) << 24);
        pl[tid + 256] = (l0 & 255) | ((l1 & 255) << 8) | ((l2 & 255) << 16)
                      | ((uint32_t)(l3 & 255) << 24);
    }
    if (tid == 0) RS[row] = mx / 32600.0f;
}

// -------------------- IMMA(hi) + DP4A(lo) GEMM -----------------------------
__global__ void __launch_bounds__(512, 1)
imma_gemm(const int8_t* __restrict__ Ah, const int8_t* __restrict__ Al,
          const float* __restrict__ rs, const int8_t* __restrict__ Bt,
          const float* __restrict__ cs, float* __restrict__ C) {
    extern __shared__ char sm[];
    const uint32_t sbase = smem_u32(sm);
    const int tid = threadIdx.x;
    const int lane = tid & 31, wid = tid >> 5;
    const int grp = lane >> 2;            // mma fragment row group
    const int tg4 = (lane & 3) * 4;       // mma fragment k byte
    const int wm = wid >> 2, wn = wid & 3;
    const int lg = lane & 3;              // dp4a row class (mod 4)
    const int lh = lane >> 2;             // dp4a col class (mod 8)

    const int e  = blockIdx.z;
    const int m0 = blockIdx.y * BM;
    const int n0 = blockIdx.x * BN;

    const int8_t* gA = Ah + ((size_t)e * TT + m0) * HH;
    const int8_t* gL = Al + ((size_t)e * TT + m0) * HH;
    const int8_t* gB = Bt + ((size_t)e * HH + n0) * HH;

    // loader: 512 threads x 2 chunks x 16B per plane
    const int lr = tid >> 3;
    const int lc = (tid & 7) << 4;
    const uint32_t sw0 =
        (uint32_t)(lr * 128 + ((((lc >> 4) ^ lr) & 7) << 4));
    const uint32_t sw1 =
        (uint32_t)((lr + 64) * 128 + ((((lc >> 4) ^ (lr + 64)) & 7) << 4));
    const size_t go0 = (size_t)lr * HH + lc;
    const size_t go1 = (size_t)(lr + 64) * HH + lc;

    // mma fragment base offsets within a plane
    uint32_t baseA[4], baseB[4];
#pragma unroll
    for (int j = 0; j < 4; j++)
        baseA[j] = (uint32_t)((wm * 32 + j * 8 + grp) * 128 + tg4);
#pragma unroll
    for (int j = 0; j < 4; j++)
        baseB[j] = (uint32_t)((wn * 32 + j * 8 + grp) * 128 + tg4);

    // dp4a base offsets (row = wm*32 + lg + 4j, col = wn*32 + lh + 8j2)
    const uint32_t dpA0 = (uint32_t)((wm * 32 + lg) * 128);
    const uint32_t dpB0 = (uint32_t)((wn * 32 + lh) * 128);

    int acc_h[2][4][4];
    int acc_lo[8][4];
#pragma unroll
    for (int a = 0; a < 2; a++)
#pragma unroll
        for (int b = 0; b < 4; b++)
#pragma unroll
            for (int c = 0; c < 4; c++) acc_h[a][b][c] = 0;
#pragma unroll
    for (int a = 0; a < 8; a++)
#pragma unroll
        for (int b = 0; b < 4; b++) acc_lo[a][b] = 0;

    // prologue: stages 0,1
#pragma unroll
    for (int p = 0; p < 2; p++) {
        const uint32_t st = sbase + p * STAGE;
        const size_t k0 = (size_t)p * BK;
        CP_ASYNC16(st + sw0,             gA + go0 + k0);
        CP_ASYNC16(st + sw1,             gA + go1 + k0);
        CP_ASYNC16(st + PLANE + sw0,     gL + go0 + k0);
        CP_ASYNC16(st + PLANE + sw1,     gL + go1 + k0);
        CP_ASYNC16(st + 2 * PLANE + sw0, gB + go0 + k0);
        CP_ASYNC16(st + 2 * PLANE + sw1, gB + go1 + k0);
        CP_COMMIT();
    }

#pragma unroll 1
    for (int i = 0; i < NKIT; i++) {
        const int s = i % NSTAGE;
        CP_WAIT1();
        __syncthreads();

        if (i + 2 < NKIT) {
            const int s2 = (i + 2) % NSTAGE;
            const uint32_t st = sbase + s2 * STAGE;
            const size_t k0 = (size_t)(i + 2) * BK;
            CP_ASYNC16(st + sw0,             gA + go0 + k0);
            CP_ASYNC16(st + sw1,             gA + go1 + k0);
            CP_ASYNC16(st + PLANE + sw0,     gL + go0 + k0);
            CP_ASYNC16(st + PLANE + sw1,     gL + go1 + k0);
            CP_ASYNC16(st + 2 * PLANE + sw0, gB + go0 + k0);
            CP_ASYNC16(st + 2 * PLANE + sw1, gB + go1 + k0);
        }
        CP_COMMIT();

        const char* stA = sm + s * STAGE;       // hi plane
        const char* stL = stA + PLANE;          // lo plane
        const char* stB = stA + 2 * PLANE;      // B plane

        // ---- hi plane on the tensor pipe ----
#pragma unroll
        for (int ks = 0; ks < 4; ks++) {
            const uint32_t xa = (uint32_t)((((2 * ks) ^ grp) & 7) << 4);
            const uint32_t xb = (uint32_t)((((2 * ks + 1) ^ grp) & 7) << 4);

            uint32_t bf[4][2];
#pragma unroll
            for (int nt = 0; nt < 4; nt++) {
                bf[nt][0] = *(const uint32_t*)(stB + baseB[nt] + xa);
                bf[nt][1] = *(const uint32_t*)(stB + baseB[nt] + xb);
            }
#pragma unroll
            for (int mt = 0; mt < 2; mt++) {
                uint32_t ah[4];
                ah[0] = *(const uint32_t*)(stA + baseA[2 * mt]     + xa);
                ah[1] = *(const uint32_t*)(stA + baseA[2 * mt + 1] + xa);
                ah[2] = *(const uint32_t*)(stA + baseA[2 * mt]     + xb);
                ah[3] = *(const uint32_t*)(stA + baseA[2 * mt + 1] + xb);
#pragma unroll
                for (int nt = 0; nt < 4; nt++) {
                    imma(acc_h[mt][nt], ah, bf[nt]);
                }
            }
        }

        // ---- lo plane on the DP4A pipe ----
#pragma unroll 4
        for (int kb = 0; kb < BK; kb += 8) {
            const uint32_t chA =
                (uint32_t)(((((kb >> 4) ^ lg) & 7) << 4) | (kb & 8));
            const uint32_t chB =
                (uint32_t)(((((kb >> 4) ^ lh) & 7) << 4) | (kb & 8));
            int2 av[8];
#pragma unroll
            for (int j = 0; j < 8; j++) {
                const uint32_t off =
                    dpA0 + (uint32_t)(j * 512) + ((j & 1) ? (chA ^ 64u) : chA);
                av[j] = *(const int2*)(stL + off);
            }
            int2 bv[4];
#pragma unroll
            for (int j2 = 0; j2 < 4; j2++) {
                bv[j2] = *(const int2*)(stB + dpB0 + (uint32_t)(j2 * 1024) + chB);
            }
#pragma unroll
            for (int j = 0; j < 8; j++)
#pragma unroll
                for (int j2 = 0; j2 < 4; j2++) {
                    acc_lo[j][j2] =
                        dp4a_(av[j].y, bv[j2].y,
                              dp4a_(av[j].x, bv[j2].x, acc_lo[j][j2]));
                }
        }
    }

    // ---------------- epilogue ----------------
    CP_WAIT0();
    __syncthreads();

    // stage dp4a lo accumulators into smem [128][128] int32 (64KB)
    int* xch = (int*)sm;
#pragma unroll
    for (int j = 0; j < 8; j++)
#pragma unroll
        for (int j2 = 0; j2 < 4; j2++) {
            const int r = wm * 32 + lg + 4 * j;
            const int c = wn * 32 + lh + 8 * j2;
            xch[r * 128 + c] = acc_lo[j][j2];
        }
    __syncthreads();

    const float* rsp = rs + (size_t)e * TT + m0;
    const float* csp = cs + (size_t)e * HH + n0;
    float* Cg = C + ((size_t)e * TT + m0) * HH + n0;

#pragma unroll
    for (int mt = 0; mt < 2; mt++) {
        const int rA = wm * 32 + mt * 16 + grp;
        const float sr0 = rsp[rA];
        const float sr1 = rsp[rA + 8];
#pragma unroll
        for (int nt = 0; nt < 4; nt++) {
            const int cn = wn * 32 + nt * 8 + (lane & 3) * 2;
            const float sc0 = csp[cn];
            const float sc1 = csp[cn + 1];
            const int* hh = acc_h[mt][nt];
            const int2 l0 = *(const int2*)(xch + rA * 128 + cn);
            const int2 l1 = *(const int2*)(xch + (rA + 8) * 128 + cn);
            float2 r0, r1;
            r0.x = fmaf(256.0f, (float)hh[0], (float)l0.x) * (sr0 * sc0);
            r0.y = fmaf(256.0f, (float)hh[1], (float)l0.y) * (sr0 * sc1);
            r1.x = fmaf(256.0f, (float)hh[2], (float)l1.x) * (sr1 * sc0);
            r1.y = fmaf(256.0f, (float)hh[3], (float)l1.y) * (sr1 * sc1);
            *(float2*)(Cg + (size_t)rA * HH + cn)       = r0;
            *(float2*)(Cg + (size_t)(rA + 8) * HH + cn) = r1;
        }
    }
}

// -------------------- launcher --------------------------------------------
extern "C" void kernel_launch(void* const* d_in, const int* in_sizes, int n_in,
                              void* d_out, int out_size) {
    const float* x   = (const float*)d_in[0];
    const int*   w1q = (const int*)d_in[1];
    const float* w1s = (const float*)d_in[2];
    const int*   w2q = (const int*)d_in[3];
    const float* w2s = (const float*)d_in[4];
    float*       out = (float*)d_out;

    void *pw1t, *pw2t, *pahi, *palo, *prs, *ph;
    cudaGetSymbolAddress(&pw1t, g_w1t);
    cudaGetSymbolAddress(&pw2t, g_w2t);
    cudaGetSymbolAddress(&pahi, g_ahi);
    cudaGetSymbolAddress(&palo, g_alo);
    cudaGetSymbolAddress(&prs,  g_rs);
    cudaGetSymbolAddress(&ph,   g_h);

    dim3 cb(32, 8), cg(HH / 32, HH / 32, EE);
    convw_kernel<<<cg, cb>>>(w1q, (int8_t*)pw1t);
    convw_kernel<<<cg, cb>>>(w2q, (int8_t*)pw2t);

    quant_kernel<<<EE * TT, 256>>>(x, (int8_t*)pahi, (int8_t*)palo,
                                   (float*)prs);

    cudaFuncSetAttribute(imma_gemm,
                         cudaFuncAttributeMaxDynamicSharedMemorySize, DYNSMEM);
    dim3 gg(HH / BN, TT / BM, EE);   // (16, 32, 8)

    imma_gemm<<<gg, 512, DYNSMEM>>>((const int8_t*)pahi, (const int8_t*)palo,
                                    (const float*)prs, (const int8_t*)pw1t,
                                    w1s, (float*)ph);

    quant_kernel<<<EE * TT, 256>>>((const float*)ph, (int8_t*)pahi,
                                   (int8_t*)palo, (float*)prs);

    imma_gemm<<<gg, 512, DYNSMEM>>>((const int8_t*)pahi, (const int8_t*)palo,
                                    (const float*)prs, (const int8_t*)pw2t,
                                    w2s, out);
}

// round 4
// speedup vs baseline: 1.3541x; 1.3541x over previous
#include <cuda_runtime.h>
#include <cstdint>

// ---------------------------------------------------------------------------
// out = ((x @ (w1_q*s1)) @ (w2_q*s2)) per expert.  E=8, T=4096, H=2048.
// Exact 16-bit activation split (hi,lo int8 planes).
// WARP-SPECIALIZED: warps 0-7 run hi-plane GEMM on the tensor pipe (IMMA),
// warps 8-15 run lo-plane GEMM on the integer pipe (DP4A), concurrently.
// out = (256*acc_hi + acc_lo) * s_row * wscale_col.
// ---------------------------------------------------------------------------

#define EE 8
#define TT 4096
#define HH 2048

#define BM 128
#define BN 128
#define BK 128
#define NKIT (HH / BK)          // 16
#define PLANE 16384             // one 128x128 s8 tile
#define STAGE (3 * PLANE)       // A_hi + A_lo + B
#define NSTAGE 3
#define DYNSMEM (NSTAGE * STAGE)  // 147456 B

// -------------------- scratch --------------------------------------------
__device__ int8_t g_w1t[(size_t)EE * HH * HH];   // w1^T int8 [E][n][k]
__device__ int8_t g_w2t[(size_t)EE * HH * HH];   // w2^T int8 [E][n][k]
__device__ int8_t g_ahi[(size_t)EE * TT * HH];   // activation hi bytes
__device__ int8_t g_alo[(size_t)EE * TT * HH];   // activation lo bytes
__device__ float  g_rs [(size_t)EE * TT];        // per-row dequant scale
__device__ float  g_h  [(size_t)EE * TT * HH];   // layer-1 output fp32

// -------------------- helpers --------------------------------------------
__device__ __forceinline__ uint32_t smem_u32(const void* p) {
    uint32_t a;
    asm("{ .reg .u64 t; cvta.to.shared.u64 t, %1; cvt.u32.u64 %0, t; }"
        : "=r"(a) : "l"(p));
    return a;
}

#define CP_ASYNC16(dst, src) \
    asm volatile("cp.async.cg.shared.global [%0], [%1], 16;" \
                 :: "r"(dst), "l"(src) : "memory")
#define CP_COMMIT() asm volatile("cp.async.commit_group;" ::: "memory")
#define CP_WAIT1()  asm volatile("cp.async.wait_group 1;" ::: "memory")
#define CP_WAIT0()  asm volatile("cp.async.wait_group 0;" ::: "memory")

__device__ __forceinline__ void imma(int* d, const uint32_t* a,
                                     const uint32_t* b) {
    asm volatile(
        "mma.sync.aligned.m16n8k32.row.col.s32.s8.s8.s32 "
        "{%0,%1,%2,%3},{%4,%5,%6,%7},{%8,%9},{%0,%1,%2,%3};"
        : "+r"(d[0]), "+r"(d[1]), "+r"(d[2]), "+r"(d[3])
        : "r"(a[0]), "r"(a[1]), "r"(a[2]), "r"(a[3]),
          "r"(b[0]), "r"(b[1]));
}

__device__ __forceinline__ int dp4a_(int a, int b, int c) {
    int d;
    asm("dp4a.s32.s32 %0, %1, %2, %3;" : "=r"(d) : "r"(a), "r"(b), "r"(c));
    return d;
}

// -------------------- weight convert + transpose --------------------------
__global__ void convw_kernel(const int* __restrict__ W,
                             int8_t* __restrict__ O) {
    __shared__ int8_t tile[32][33];
    const int e  = blockIdx.z;
    const int n0 = blockIdx.x * 32;
    const int k0 = blockIdx.y * 32;
    const int tx = threadIdx.x, ty = threadIdx.y;

    const int* src = W + ((size_t)e * HH + k0) * HH + n0;
#pragma unroll
    for (int r = 0; r < 4; r++) {
        tile[ty + r * 8][tx] = (int8_t)src[(size_t)(ty + r * 8) * HH + tx];
    }
    __syncthreads();
    const int t  = ty * 32 + tx;
    const int nr = t >> 3;
    const int c4 = (t & 7) * 4;
    uint32_t p = (uint32_t)(uint8_t)tile[c4 + 0][nr]
               | ((uint32_t)(uint8_t)tile[c4 + 1][nr] << 8)
               | ((uint32_t)(uint8_t)tile[c4 + 2][nr] << 16)
               | ((uint32_t)(uint8_t)tile[c4 + 3][nr] << 24);
    *(uint32_t*)(O + ((size_t)e * HH + n0 + nr) * HH + k0 + c4) = p;
}

// -------------------- activation quantize (16-bit split) -------------------
__global__ void quant_kernel(const float* __restrict__ X,
                             int8_t* __restrict__ Qh,
                             int8_t* __restrict__ Ql,
                             float* __restrict__ RS) {
    const int row = blockIdx.x;
    const float* x = X + (size_t)row * HH;
    const int tid = threadIdx.x;

    const float4 v0 = ((const float4*)x)[tid];
    const float4 v1 = ((const float4*)x)[tid + 256];

    float m = fabsf(v0.x);
    m = fmaxf(m, fabsf(v0.y)); m = fmaxf(m, fabsf(v0.z));
    m = fmaxf(m, fabsf(v0.w)); m = fmaxf(m, fabsf(v1.x));
    m = fmaxf(m, fabsf(v1.y)); m = fmaxf(m, fabsf(v1.z));
    m = fmaxf(m, fabsf(v1.w));
#pragma unroll
    for (int o = 16; o; o >>= 1)
        m = fmaxf(m, __shfl_xor_sync(0xFFFFFFFFu, m, o));
    __shared__ float wr[8];
    if ((tid & 31) == 0) wr[tid >> 5] = m;
    __syncthreads();
    float mx = wr[0];
#pragma unroll
    for (int j = 1; j < 8; j++) mx = fmaxf(mx, wr[j]);
    mx = fmaxf(mx, 1e-20f);
    const float inv = 32600.0f / mx;

    uint32_t* ph = (uint32_t*)(Qh + (size_t)row * HH);
    uint32_t* pl = (uint32_t*)(Ql + (size_t)row * HH);

    {
        const int q0 = __float2int_rn(v0.x * inv);
        const int q1 = __float2int_rn(v0.y * inv);
        const int q2 = __float2int_rn(v0.z * inv);
        const int q3 = __float2int_rn(v0.w * inv);
        const int h0 = (q0 + 128) >> 8, h1 = (q1 + 128) >> 8;
        const int h2 = (q2 + 128) >> 8, h3 = (q3 + 128) >> 8;
        const int l0 = q0 - (h0 << 8), l1 = q1 - (h1 << 8);
        const int l2 = q2 - (h2 << 8), l3 = q3 - (h3 << 8);
        ph[tid] = (h0 & 255) | ((h1 & 255) << 8) | ((h2 & 255) << 16)
                | ((uint32_t)(h3 & 255) << 24);
        pl[tid] = (l0 & 255) | ((l1 & 255) << 8) | ((l2 & 255) << 16)
                | ((uint32_t)(l3 & 255) << 24);
    }
    {
        const int q0 = __float2int_rn(v1.x * inv);
        const int q1 = __float2int_rn(v1.y * inv);
        const int q2 = __float2int_rn(v1.z * inv);
        const int q3 = __float2int_rn(v1.w * inv);
        const int h0 = (q0 + 128) >> 8, h1 = (q1 + 128) >> 8;
        const int h2 = (q2 + 128) >> 8, h3 = (q3 + 128) >> 8;
        const int l0 = q0 - (h0 << 8), l1 = q1 - (h1 << 8);
        const int l2 = q2 - (h2 << 8), l3 = q3 - (h3 << 8);
        ph[tid + 256] = (h0 & 255) | ((h1 & 255) << 8) | ((h2 & 255) << 16)
                      | ((uint32_t)(h3 & 255) << 24);
        pl[tid + 256] = (l0 & 255) | ((l1 & 255) << 8) | ((l2 & 255) << 16)
                      | ((uint32_t)(l3 & 255) << 24);
    }
    if (tid == 0) RS[row] = mx / 32600.0f;
}

// -------------------- warp-specialized GEMM --------------------------------
// warps 0-7:  hi plane, IMMA, warp tile 64(m) x 32(n)
// warps 8-15: lo plane, DP4A, warp tile 32(m) x 64(n)
__global__ void __launch_bounds__(512, 1)
imma_gemm(const int8_t* __restrict__ Ah, const int8_t* __restrict__ Al,
          const float* __restrict__ rs, const int8_t* __restrict__ Bt,
          const float* __restrict__ cs, float* __restrict__ C) {
    extern __shared__ char sm[];
    const uint32_t sbase = smem_u32(sm);
    const int tid = threadIdx.x;
    const int lane = tid & 31, wid = tid >> 5;

    const int e  = blockIdx.z;
    const int m0 = blockIdx.y * BM;
    const int n0 = blockIdx.x * BN;

    const int8_t* gA = Ah + ((size_t)e * TT + m0) * HH;
    const int8_t* gL = Al + ((size_t)e * TT + m0) * HH;
    const int8_t* gB = Bt + ((size_t)e * HH + n0) * HH;

    // loader addressing (all 512 threads, 2x16B per plane)
    const int lr = tid >> 3;
    const int lc = (tid & 7) << 4;
    const uint32_t sw0 =
        (uint32_t)(lr * 128 + ((((lc >> 4) ^ lr) & 7) << 4));
    const uint32_t sw1 =
        (uint32_t)((lr + 64) * 128 + ((((lc >> 4) ^ (lr + 64)) & 7) << 4));
    const size_t go0 = (size_t)lr * HH + lc;
    const size_t go1 = (size_t)(lr + 64) * HH + lc;

    // ---- mma-warp config (wid 0..7) ----
    const int grp = lane >> 2;
    const int tg4 = (lane & 3) * 4;
    const int wm = wid >> 2;            // 0..1 -> 64 rows
    const int wn = wid & 3;             // 0..3 -> 32 cols
    uint32_t baseA[8], baseB[4];
#pragma unroll
    for (int j = 0; j < 8; j++)
        baseA[j] = (uint32_t)((wm * 64 + j * 8 + grp) * 128 + tg4);
#pragma unroll
    for (int j = 0; j < 4; j++)
        baseB[j] = (uint32_t)((wn * 32 + j * 8 + grp) * 128 + tg4);

    // ---- dp4a-warp config (wid 8..15) ----
    const int dwid = wid - 8;
    const int wtr = dwid >> 1;          // 0..3 -> rows wtr*32
    const int wtc = dwid & 1;           // 0..1 -> cols wtc*64
    const int lg = lane & 3;            // row class
    const int lh = lane >> 2;           // col class 0..7
    const uint32_t dpA0 = (uint32_t)((wtr * 32 + lg) * 128);
    const uint32_t dpB0 = (uint32_t)((wtc * 64 + lh) * 128);

    int acc_h[4][4][4];                 // mma warps: 64 accs
    int acc_lo[8][8];                   // dp4a warps: 64 accs
    if (wid < 8) {
#pragma unroll
        for (int a = 0; a < 4; a++)
#pragma unroll
            for (int b = 0; b < 4; b++)
#pragma unroll
                for (int c = 0; c < 4; c++) acc_h[a][b][c] = 0;
    } else {
#pragma unroll
        for (int a = 0; a < 8; a++)
#pragma unroll
            for (int b = 0; b < 8; b++) acc_lo[a][b] = 0;
    }

    // prologue: stages 0,1
#pragma unroll
    for (int p = 0; p < 2; p++) {
        const uint32_t st = sbase + p * STAGE;
        const size_t k0 = (size_t)p * BK;
        CP_ASYNC16(st + sw0,             gA + go0 + k0);
        CP_ASYNC16(st + sw1,             gA + go1 + k0);
        CP_ASYNC16(st + PLANE + sw0,     gL + go0 + k0);
        CP_ASYNC16(st + PLANE + sw1,     gL + go1 + k0);
        CP_ASYNC16(st + 2 * PLANE + sw0, gB + go0 + k0);
        CP_ASYNC16(st + 2 * PLANE + sw1, gB + go1 + k0);
        CP_COMMIT();
    }

#pragma unroll 1
    for (int i = 0; i < NKIT; i++) {
        const int s = i % NSTAGE;
        CP_WAIT1();
        __syncthreads();

        if (i + 2 < NKIT) {
            const int s2 = (i + 2) % NSTAGE;
            const uint32_t st = sbase + s2 * STAGE;
            const size_t k0 = (size_t)(i + 2) * BK;
            CP_ASYNC16(st + sw0,             gA + go0 + k0);
            CP_ASYNC16(st + sw1,             gA + go1 + k0);
            CP_ASYNC16(st + PLANE + sw0,     gL + go0 + k0);
            CP_ASYNC16(st + PLANE + sw1,     gL + go1 + k0);
            CP_ASYNC16(st + 2 * PLANE + sw0, gB + go0 + k0);
            CP_ASYNC16(st + 2 * PLANE + sw1, gB + go1 + k0);
        }
        CP_COMMIT();

        const char* stA = sm + s * STAGE;       // hi plane
        const char* stL = stA + PLANE;          // lo plane
        const char* stB = stA + 2 * PLANE;      // B plane

        if (wid < 8) {
            // ================= tensor pipe: hi plane =================
#pragma unroll
            for (int ks = 0; ks < 4; ks++) {
                const uint32_t xa = (uint32_t)((((2 * ks) ^ grp) & 7) << 4);
                const uint32_t xb = (uint32_t)((((2 * ks + 1) ^ grp) & 7) << 4);

                uint32_t bf[4][2];
#pragma unroll
                for (int nt = 0; nt < 4; nt++) {
                    bf[nt][0] = *(const uint32_t*)(stB + baseB[nt] + xa);
                    bf[nt][1] = *(const uint32_t*)(stB + baseB[nt] + xb);
                }
#pragma unroll
                for (int mt = 0; mt < 4; mt++) {
                    uint32_t ah[4];
                    ah[0] = *(const uint32_t*)(stA + baseA[2 * mt]     + xa);
                    ah[1] = *(const uint32_t*)(stA + baseA[2 * mt + 1] + xa);
                    ah[2] = *(const uint32_t*)(stA + baseA[2 * mt]     + xb);
                    ah[3] = *(const uint32_t*)(stA + baseA[2 * mt + 1] + xb);
#pragma unroll
                    for (int nt = 0; nt < 4; nt++) {
                        imma(acc_h[mt][nt], ah, bf[nt]);
                    }
                }
            }
        } else {
            // ================= integer pipe: lo plane =================
#pragma unroll 4
            for (int kb = 0; kb < BK; kb += 8) {
                const uint32_t chA =
                    (uint32_t)(((((kb >> 4) ^ lg) & 7) << 4) | (kb & 8));
                const uint32_t chB =
                    (uint32_t)(((((kb >> 4) ^ lh) & 7) << 4) | (kb & 8));
                int2 av[8];
#pragma unroll
                for (int j = 0; j < 8; j++) {
                    const uint32_t off = dpA0 + (uint32_t)(j * 512)
                                       + ((j & 1) ? (chA ^ 64u) : chA);
                    av[j] = *(const int2*)(stL + off);
                }
                int2 bv[8];
#pragma unroll
                for (int j2 = 0; j2 < 8; j2++) {
                    bv[j2] = *(const int2*)(stB + dpB0
                                            + (uint32_t)(j2 * 1024) + chB);
                }
#pragma unroll
                for (int j = 0; j < 8; j++)
#pragma unroll
                    for (int j2 = 0; j2 < 8; j2++) {
                        acc_lo[j][j2] =
                            dp4a_(av[j].y, bv[j2].y,
                                  dp4a_(av[j].x, bv[j2].x, acc_lo[j][j2]));
                    }
            }
        }
    }

    // ---------------- epilogue ----------------
    CP_WAIT0();
    __syncthreads();

    int* xch = (int*)sm;                // 128x128 int32 (64KB) in stage mem
    if (wid >= 8) {
#pragma unroll
        for (int j = 0; j < 8; j++)
#pragma unroll
            for (int j2 = 0; j2 < 8; j2++) {
                const int r = wtr * 32 + lg + 4 * j;
                const int c = wtc * 64 + lh + 8 * j2;
                xch[r * 128 + c] = acc_lo[j][j2];
            }
    }
    __syncthreads();

    if (wid < 8) {
        const float* rsp = rs + (size_t)e * TT + m0;
        const float* csp = cs + (size_t)e * HH + n0;
        float* Cg = C + ((size_t)e * TT + m0) * HH + n0;

#pragma unroll
        for (int mt = 0; mt < 4; mt++) {
            const int rA = wm * 64 + mt * 16 + grp;
            const float sr0 = rsp[rA];
            const float sr1 = rsp[rA + 8];
#pragma unroll
            for (int nt = 0; nt < 4; nt++) {
                const int cn = wn * 32 + nt * 8 + (lane & 3) * 2;
                const float sc0 = csp[cn];
                const float sc1 = csp[cn + 1];
                const int* hh = acc_h[mt][nt];
                const int2 l0 = *(const int2*)(xch + rA * 128 + cn);
                const int2 l1 = *(const int2*)(xch + (rA + 8) * 128 + cn);
                float2 r0, r1;
                r0.x = fmaf(256.0f, (float)hh[0], (float)l0.x) * (sr0 * sc0);
                r0.y = fmaf(256.0f, (float)hh[1], (float)l0.y) * (sr0 * sc1);
                r1.x = fmaf(256.0f, (float)hh[2], (float)l1.x) * (sr1 * sc0);
                r1.y = fmaf(256.0f, (float)hh[3], (float)l1.y) * (sr1 * sc1);
                *(float2*)(Cg + (size_t)rA * HH + cn)       = r0;
                *(float2*)(Cg + (size_t)(rA + 8) * HH + cn) = r1;
            }
        }
    }
}

// -------------------- launcher --------------------------------------------
extern "C" void kernel_launch(void* const* d_in, const int* in_sizes, int n_in,
                              void* d_out, int out_size) {
    const float* x   = (const float*)d_in[0];
    const int*   w1q = (const int*)d_in[1];
    const float* w1s = (const float*)d_in[2];
    const int*   w2q = (const int*)d_in[3];
    const float* w2s = (const float*)d_in[4];
    float*       out = (float*)d_out;

    void *pw1t, *pw2t, *pahi, *palo, *prs, *ph;
    cudaGetSymbolAddress(&pw1t, g_w1t);
    cudaGetSymbolAddress(&pw2t, g_w2t);
    cudaGetSymbolAddress(&pahi, g_ahi);
    cudaGetSymbolAddress(&palo, g_alo);
    cudaGetSymbolAddress(&prs,  g_rs);
    cudaGetSymbolAddress(&ph,   g_h);

    dim3 cb(32, 8), cg(HH / 32, HH / 32, EE);
    convw_kernel<<<cg, cb>>>(w1q, (int8_t*)pw1t);
    convw_kernel<<<cg, cb>>>(w2q, (int8_t*)pw2t);

    quant_kernel<<<EE * TT, 256>>>(x, (int8_t*)pahi, (int8_t*)palo,
                                   (float*)prs);

    cudaFuncSetAttribute(imma_gemm,
                         cudaFuncAttributeMaxDynamicSharedMemorySize, DYNSMEM);
    dim3 gg(HH / BN, TT / BM, EE);   // (16, 32, 8)

    imma_gemm<<<gg, 512, DYNSMEM>>>((const int8_t*)pahi, (const int8_t*)palo,
                                    (const float*)prs, (const int8_t*)pw1t,
                                    w1s, (float*)ph);

    quant_kernel<<<EE * TT, 256>>>((const float*)ph, (int8_t*)pahi,
                                   (int8_t*)palo, (float*)prs);

    imma_gemm<<<gg, 512, DYNSMEM>>>((const int8_t*)pahi, (const int8_t*)palo,
                                    (const float*)prs, (const int8_t*)pw2t,
                                    w2s, out);
}

// round 5
// speedup vs baseline: 1.3553x; 1.0008x over previous
#include <cuda_runtime.h>
#include <cstdint>

// ---------------------------------------------------------------------------
// out = ((x @ (w1_q*s1)) @ (w2_q*s2)) per expert.  E=8, T=4096, H=2048.
// Exact 16-bit activation split (hi,lo int8 planes).
// WARP-SPECIALIZED: warps 0-7 run hi-plane GEMM on the tensor pipe (IMMA),
// warps 8-15 run lo-plane GEMM on the integer pipe (DP4A), concurrently.
// 4-stage cp.async ring, 2 k-iters consumed per barrier window.
// out = (256*acc_hi + acc_lo) * s_row * wscale_col.
// ---------------------------------------------------------------------------

#define EE 8
#define TT 4096
#define HH 2048

#define BM 128
#define BN 128
#define BK 128
#define NKIT (HH / BK)          // 16
#define PLANE 16384             // one 128x128 s8 tile
#define STAGE (3 * PLANE)       // A_hi + A_lo + B
#define NSTAGE 4
#define DYNSMEM (NSTAGE * STAGE)  // 196608 B

// -------------------- scratch --------------------------------------------
__device__ int8_t g_w1t[(size_t)EE * HH * HH];   // w1^T int8 [E][n][k]
__device__ int8_t g_w2t[(size_t)EE * HH * HH];   // w2^T int8 [E][n][k]
__device__ int8_t g_ahi[(size_t)EE * TT * HH];   // activation hi bytes
__device__ int8_t g_alo[(size_t)EE * TT * HH];   // activation lo bytes
__device__ float  g_rs [(size_t)EE * TT];        // per-row dequant scale
__device__ float  g_h  [(size_t)EE * TT * HH];   // layer-1 output fp32

// -------------------- helpers --------------------------------------------
__device__ __forceinline__ uint32_t smem_u32(const void* p) {
    uint32_t a;
    asm("{ .reg .u64 t; cvta.to.shared.u64 t, %1; cvt.u32.u64 %0, t; }"
        : "=r"(a) : "l"(p));
    return a;
}

#define CP_ASYNC16(dst, src) \
    asm volatile("cp.async.cg.shared.global [%0], [%1], 16;" \
                 :: "r"(dst), "l"(src) : "memory")
#define CP_COMMIT() asm volatile("cp.async.commit_group;" ::: "memory")
#define CP_WAIT2()  asm volatile("cp.async.wait_group 2;" ::: "memory")
#define CP_WAIT0()  asm volatile("cp.async.wait_group 0;" ::: "memory")

__device__ __forceinline__ void imma(int* d, const uint32_t* a,
                                     const uint32_t* b) {
    asm volatile(
        "mma.sync.aligned.m16n8k32.row.col.s32.s8.s8.s32 "
        "{%0,%1,%2,%3},{%4,%5,%6,%7},{%8,%9},{%0,%1,%2,%3};"
        : "+r"(d[0]), "+r"(d[1]), "+r"(d[2]), "+r"(d[3])
        : "r"(a[0]), "r"(a[1]), "r"(a[2]), "r"(a[3]),
          "r"(b[0]), "r"(b[1]));
}

__device__ __forceinline__ int dp4a_(int a, int b, int c) {
    int d;
    asm("dp4a.s32.s32 %0, %1, %2, %3;" : "=r"(d) : "r"(a), "r"(b), "r"(c));
    return d;
}

// -------------------- weight convert + transpose --------------------------
__global__ void convw_kernel(const int* __restrict__ W,
                             int8_t* __restrict__ O) {
    __shared__ int8_t tile[32][33];
    const int e  = blockIdx.z;
    const int n0 = blockIdx.x * 32;
    const int k0 = blockIdx.y * 32;
    const int tx = threadIdx.x, ty = threadIdx.y;

    const int* src = W + ((size_t)e * HH + k0) * HH + n0;
#pragma unroll
    for (int r = 0; r < 4; r++) {
        tile[ty + r * 8][tx] = (int8_t)src[(size_t)(ty + r * 8) * HH + tx];
    }
    __syncthreads();
    const int t  = ty * 32 + tx;
    const int nr = t >> 3;
    const int c4 = (t & 7) * 4;
    uint32_t p = (uint32_t)(uint8_t)tile[c4 + 0][nr]
               | ((uint32_t)(uint8_t)tile[c4 + 1][nr] << 8)
               | ((uint32_t)(uint8_t)tile[c4 + 2][nr] << 16)
               | ((uint32_t)(uint8_t)tile[c4 + 3][nr] << 24);
    *(uint32_t*)(O + ((size_t)e * HH + n0 + nr) * HH + k0 + c4) = p;
}

// -------------------- activation quantize (16-bit split) -------------------
__global__ void quant_kernel(const float* __restrict__ X,
                             int8_t* __restrict__ Qh,
                             int8_t* __restrict__ Ql,
                             float* __restrict__ RS) {
    const int row = blockIdx.x;
    const float* x = X + (size_t)row * HH;
    const int tid = threadIdx.x;

    const float4 v0 = ((const float4*)x)[tid];
    const float4 v1 = ((const float4*)x)[tid + 256];

    float m = fabsf(v0.x);
    m = fmaxf(m, fabsf(v0.y)); m = fmaxf(m, fabsf(v0.z));
    m = fmaxf(m, fabsf(v0.w)); m = fmaxf(m, fabsf(v1.x));
    m = fmaxf(m, fabsf(v1.y)); m = fmaxf(m, fabsf(v1.z));
    m = fmaxf(m, fabsf(v1.w));
#pragma unroll
    for (int o = 16; o; o >>= 1)
        m = fmaxf(m, __shfl_xor_sync(0xFFFFFFFFu, m, o));
    __shared__ float wr[8];
    if ((tid & 31) == 0) wr[tid >> 5] = m;
    __syncthreads();
    float mx = wr[0];
#pragma unroll
    for (int j = 1; j < 8; j++) mx = fmaxf(mx, wr[j]);
    mx = fmaxf(mx, 1e-20f);
    const float inv = 32600.0f / mx;

    uint32_t* ph = (uint32_t*)(Qh + (size_t)row * HH);
    uint32_t* pl = (uint32_t*)(Ql + (size_t)row * HH);

    {
        const int q0 = __float2int_rn(v0.x * inv);
        const int q1 = __float2int_rn(v0.y * inv);
        const int q2 = __float2int_rn(v0.z * inv);
        const int q3 = __float2int_rn(v0.w * inv);
        const int h0 = (q0 + 128) >> 8, h1 = (q1 + 128) >> 8;
        const int h2 = (q2 + 128) >> 8, h3 = (q3 + 128) >> 8;
        const int l0 = q0 - (h0 << 8), l1 = q1 - (h1 << 8);
        const int l2 = q2 - (h2 << 8), l3 = q3 - (h3 << 8);
        ph[tid] = (h0 & 255) | ((h1 & 255) << 8) | ((h2 & 255) << 16)
                | ((uint32_t)(h3 & 255) << 24);
        pl[tid] = (l0 & 255) | ((l1 & 255) << 8) | ((l2 & 255) << 16)
                | ((uint32_t)(l3 & 255) << 24);
    }
    {
        const int q0 = __float2int_rn(v1.x * inv);
        const int q1 = __float2int_rn(v1.y * inv);
        const int q2 = __float2int_rn(v1.z * inv);
        const int q3 = __float2int_rn(v1.w * inv);
        const int h0 = (q0 + 128) >> 8, h1 = (q1 + 128) >> 8;
        const int h2 = (q2 + 128) >> 8, h3 = (q3 + 128) >> 8;
        const int l0 = q0 - (h0 << 8), l1 = q1 - (h1 << 8);
        const int l2 = q2 - (h2 << 8), l3 = q3 - (h3 << 8);
        ph[tid + 256] = (h0 & 255) | ((h1 & 255) << 8) | ((h2 & 255) << 16)
                      | ((uint32_t)(h3 & 255) << 24);
        pl[tid + 256] = (l0 & 255) | ((l1 & 255) << 8) | ((l2 & 255) << 16)
                      | ((uint32_t)(l3 & 255) << 24);
    }
    if (tid == 0) RS[row] = mx / 32600.0f;
}

// -------------------- warp-specialized GEMM --------------------------------
// warps 0-7:  hi plane, IMMA, warp tile 64(m) x 32(n)
// warps 8-15: lo plane, DP4A, warp tile 32(m) x 64(n)
__global__ void __launch_bounds__(512, 1)
imma_gemm(const int8_t* __restrict__ Ah, const int8_t* __restrict__ Al,
          const float* __restrict__ rs, const int8_t* __restrict__ Bt,
          const float* __restrict__ cs, float* __restrict__ C) {
    extern __shared__ char sm[];
    const uint32_t sbase = smem_u32(sm);
    const int tid = threadIdx.x;
    const int lane = tid & 31, wid = tid >> 5;

    const int e  = blockIdx.z;
    const int m0 = blockIdx.y * BM;
    const int n0 = blockIdx.x * BN;

    const int8_t* gA = Ah + ((size_t)e * TT + m0) * HH;
    const int8_t* gL = Al + ((size_t)e * TT + m0) * HH;
    const int8_t* gB = Bt + ((size_t)e * HH + n0) * HH;

    // loader addressing (all 512 threads, 2x16B per plane)
    const int lr = tid >> 3;
    const int lc = (tid & 7) << 4;
    const uint32_t sw0 =
        (uint32_t)(lr * 128 + ((((lc >> 4) ^ lr) & 7) << 4));
    const uint32_t sw1 =
        (uint32_t)((lr + 64) * 128 + ((((lc >> 4) ^ (lr + 64)) & 7) << 4));
    const size_t go0 = (size_t)lr * HH + lc;
    const size_t go1 = (size_t)(lr + 64) * HH + lc;

    // ---- mma-warp config (wid 0..7) ----
    const int grp = lane >> 2;
    const int tg4 = (lane & 3) * 4;
    const int wm = wid >> 2;            // 0..1 -> 64 rows
    const int wn = wid & 3;             // 0..3 -> 32 cols
    uint32_t baseA[8], baseB[4];
#pragma unroll
    for (int j = 0; j < 8; j++)
        baseA[j] = (uint32_t)((wm * 64 + j * 8 + grp) * 128 + tg4);
#pragma unroll
    for (int j = 0; j < 4; j++)
        baseB[j] = (uint32_t)((wn * 32 + j * 8 + grp) * 128 + tg4);

    // ---- dp4a-warp config (wid 8..15) ----
    const int dwid = wid - 8;
    const int wtr = dwid >> 1;          // 0..3 -> rows wtr*32
    const int wtc = dwid & 1;           // 0..1 -> cols wtc*64
    const int lg = lane & 3;            // row class
    const int lh = lane >> 2;           // col class 0..7
    const uint32_t dpA0 = (uint32_t)((wtr * 32 + lg) * 128);
    const uint32_t dpB0 = (uint32_t)((wtc * 64 + lh) * 128);

    int acc_h[4][4][4];                 // mma warps: 64 accs
    int acc_lo[8][8];                   // dp4a warps: 64 accs
    if (wid < 8) {
#pragma unroll
        for (int a = 0; a < 4; a++)
#pragma unroll
            for (int b = 0; b < 4; b++)
#pragma unroll
                for (int c = 0; c < 4; c++) acc_h[a][b][c] = 0;
    } else {
#pragma unroll
        for (int a = 0; a < 8; a++)
#pragma unroll
            for (int b = 0; b < 8; b++) acc_lo[a][b] = 0;
    }

    // prologue: fill stages 0..3 with k-iters 0..3
#pragma unroll
    for (int p = 0; p < NSTAGE; p++) {
        const uint32_t st = sbase + p * STAGE;
        const size_t k0 = (size_t)p * BK;
        CP_ASYNC16(st + sw0,             gA + go0 + k0);
        CP_ASYNC16(st + sw1,             gA + go1 + k0);
        CP_ASYNC16(st + PLANE + sw0,     gL + go0 + k0);
        CP_ASYNC16(st + PLANE + sw1,     gL + go1 + k0);
        CP_ASYNC16(st + 2 * PLANE + sw0, gB + go0 + k0);
        CP_ASYNC16(st + 2 * PLANE + sw1, gB + go1 + k0);
        CP_COMMIT();
    }

    // windows: consume stage pair, 2 k-iters per barrier window
#pragma unroll 1
    for (int w = 0; w < NKIT / 2; w++) {
        if (w < NKIT / 2 - 1) { CP_WAIT2(); } else { CP_WAIT0(); }
        __syncthreads();
        const int sp = (w & 1) * 2;     // stage pair base

        if (wid < 8) {
            // ================= tensor pipe: hi plane =================
#pragma unroll
            for (int t = 0; t < 2; t++) {
                const char* stA = sm + (sp + t) * STAGE;
                const char* stB = stA + 2 * PLANE;
#pragma unroll
                for (int ks = 0; ks < 4; ks++) {
                    const uint32_t xa =
                        (uint32_t)((((2 * ks) ^ grp) & 7) << 4);
                    const uint32_t xb =
                        (uint32_t)((((2 * ks + 1) ^ grp) & 7) << 4);

                    uint32_t bf[4][2];
#pragma unroll
                    for (int nt = 0; nt < 4; nt++) {
                        bf[nt][0] = *(const uint32_t*)(stB + baseB[nt] + xa);
                        bf[nt][1] = *(const uint32_t*)(stB + baseB[nt] + xb);
                    }
#pragma unroll
                    for (int mt = 0; mt < 4; mt++) {
                        uint32_t ah[4];
                        ah[0] = *(const uint32_t*)(stA + baseA[2 * mt]     + xa);
                        ah[1] = *(const uint32_t*)(stA + baseA[2 * mt + 1] + xa);
                        ah[2] = *(const uint32_t*)(stA + baseA[2 * mt]     + xb);
                        ah[3] = *(const uint32_t*)(stA + baseA[2 * mt + 1] + xb);
#pragma unroll
                        for (int nt = 0; nt < 4; nt++) {
                            imma(acc_h[mt][nt], ah, bf[nt]);
                        }
                    }
                }
            }
        } else {
            // ================= integer pipe: lo plane =================
#pragma unroll
            for (int t = 0; t < 2; t++) {
                const char* stL = sm + (sp + t) * STAGE + PLANE;
                const char* stB = sm + (sp + t) * STAGE + 2 * PLANE;
#pragma unroll 2
                for (int kb = 0; kb < BK; kb += 16) {
                    const uint32_t cA0 =
                        (uint32_t)(((((kb >> 4)) ^ lg) & 7) << 4);
                    const uint32_t cA1 = cA0 ^ 64u;
                    const uint32_t cB =
                        (uint32_t)(((((kb >> 4)) ^ lh) & 7) << 4);
                    int4 bv[8];
#pragma unroll
                    for (int j2 = 0; j2 < 8; j2++) {
                        bv[j2] = *(const int4*)(stB + dpB0
                                                + (uint32_t)(j2 * 1024) + cB);
                    }
#pragma unroll
                    for (int j = 0; j < 8; j++) {
                        const int4 a = *(const int4*)(stL + dpA0
                                         + (uint32_t)(j * 512)
                                         + ((j & 1) ? cA1 : cA0));
#pragma unroll
                        for (int j2 = 0; j2 < 8; j2++) {
                            acc_lo[j][j2] =
                                dp4a_(a.x, bv[j2].x,
                                dp4a_(a.y, bv[j2].y,
                                dp4a_(a.z, bv[j2].z,
                                dp4a_(a.w, bv[j2].w, acc_lo[j][j2]))));
                        }
                    }
                }
            }
        }
        __syncthreads();

        // refill the consumed pair with k-iters 2w+4, 2w+5
        if (w < NKIT / 2 - 2) {
#pragma unroll
            for (int t = 0; t < 2; t++) {
                const uint32_t st = sbase + (sp + t) * STAGE;
                const size_t k0 = (size_t)(2 * w + 4 + t) * BK;
                CP_ASYNC16(st + sw0,             gA + go0 + k0);
                CP_ASYNC16(st + sw1,             gA + go1 + k0);
                CP_ASYNC16(st + PLANE + sw0,     gL + go0 + k0);
                CP_ASYNC16(st + PLANE + sw1,     gL + go1 + k0);
                CP_ASYNC16(st + 2 * PLANE + sw0, gB + go0 + k0);
                CP_ASYNC16(st + 2 * PLANE + sw1, gB + go1 + k0);
                CP_COMMIT();
            }
        }
    }

    // ---------------- epilogue ----------------
    __syncthreads();

    int* xch = (int*)sm;                // 128x128 int32 (64KB) in stage mem
    if (wid >= 8) {
#pragma unroll
        for (int j = 0; j < 8; j++)
#pragma unroll
            for (int j2 = 0; j2 < 8; j2++) {
                const int r = wtr * 32 + lg + 4 * j;
                const int c = wtc * 64 + lh + 8 * j2;
                xch[r * 128 + c] = acc_lo[j][j2];
            }
    }
    __syncthreads();

    if (wid < 8) {
        const float* rsp = rs + (size_t)e * TT + m0;
        const float* csp = cs + (size_t)e * HH + n0;
        float* Cg = C + ((size_t)e * TT + m0) * HH + n0;

#pragma unroll
        for (int mt = 0; mt < 4; mt++) {
            const int rA = wm * 64 + mt * 16 + grp;
            const float sr0 = rsp[rA];
            const float sr1 = rsp[rA + 8];
#pragma unroll
            for (int nt = 0; nt < 4; nt++) {
                const int cn = wn * 32 + nt * 8 + (lane & 3) * 2;
                const float sc0 = csp[cn];
                const float sc1 = csp[cn + 1];
                const int* hh = acc_h[mt][nt];
                const int2 l0 = *(const int2*)(xch + rA * 128 + cn);
                const int2 l1 = *(const int2*)(xch + (rA + 8) * 128 + cn);
                float2 r0, r1;
                r0.x = fmaf(256.0f, (float)hh[0], (float)l0.x) * (sr0 * sc0);
                r0.y = fmaf(256.0f, (float)hh[1], (float)l0.y) * (sr0 * sc1);
                r1.x = fmaf(256.0f, (float)hh[2], (float)l1.x) * (sr1 * sc0);
                r1.y = fmaf(256.0f, (float)hh[3], (float)l1.y) * (sr1 * sc1);
                *(float2*)(Cg + (size_t)rA * HH + cn)       = r0;
                *(float2*)(Cg + (size_t)(rA + 8) * HH + cn) = r1;
            }
        }
    }
}

// -------------------- launcher --------------------------------------------
extern "C" void kernel_launch(void* const* d_in, const int* in_sizes, int n_in,
                              void* d_out, int out_size) {
    const float* x   = (const float*)d_in[0];
    const int*   w1q = (const int*)d_in[1];
    const float* w1s = (const float*)d_in[2];
    const int*   w2q = (const int*)d_in[3];
    const float* w2s = (const float*)d_in[4];
    float*       out = (float*)d_out;

    void *pw1t, *pw2t, *pahi, *palo, *prs, *ph;
    cudaGetSymbolAddress(&pw1t, g_w1t);
    cudaGetSymbolAddress(&pw2t, g_w2t);
    cudaGetSymbolAddress(&pahi, g_ahi);
    cudaGetSymbolAddress(&palo, g_alo);
    cudaGetSymbolAddress(&prs,  g_rs);
    cudaGetSymbolAddress(&ph,   g_h);

    dim3 cb(32, 8), cg(HH / 32, HH / 32, EE);
    convw_kernel<<<cg, cb>>>(w1q, (int8_t*)pw1t);
    convw_kernel<<<cg, cb>>>(w2q, (int8_t*)pw2t);

    quant_kernel<<<EE * TT, 256>>>(x, (int8_t*)pahi, (int8_t*)palo,
                                   (float*)prs);

    cudaFuncSetAttribute(imma_gemm,
                         cudaFuncAttributeMaxDynamicSharedMemorySize, DYNSMEM);
    dim3 gg(HH / BN, TT / BM, EE);   // (16, 32, 8)

    imma_gemm<<<gg, 512, DYNSMEM>>>((const int8_t*)pahi, (const int8_t*)palo,
                                    (const float*)prs, (const int8_t*)pw1t,
                                    w1s, (float*)ph);

    quant_kernel<<<EE * TT, 256>>>((const float*)ph, (int8_t*)pahi,
                                   (int8_t*)palo, (float*)prs);

    imma_gemm<<<gg, 512, DYNSMEM>>>((const int8_t*)pahi, (const int8_t*)palo,
                                    (const float*)prs, (const int8_t*)pw2t,
                                    w2s, out);
}